// round 15
// baseline (speedup 1.0000x reference)
#include <cuda_runtime.h>
#include <cuda_bf16.h>
#include <math.h>
#include <stdint.h>

// Shapes (fixed): B*N=6400 rows, K=1024 noise, D=64, V=1e6.
#define DIM        64
#define K_NOISE    1024
#define ROWS_TOT   6400
#define MT         128                 // M tile (rows per CTA)
#define NT         64                  // N tile (noise cols per CTA)
#define A_BYTES    (MT * 128)          // 16 KB
#define B_BYTES    (NT * 128)          // 8 KB
#define GRID_M     (ROWS_TOT / MT)     // 50
#define GRID_N     (K_NOISE / NT)      // 16
#define NTHREADS   256
#define TROWS      (MT / GRID_N)       // 8 target rows per CTA
#define LOG2E      1.4426950408889634f

typedef unsigned long long u64;

// ---------------------------------------------------------------------------
// helpers
// ---------------------------------------------------------------------------
static __device__ __forceinline__ uint32_t smem_u32(const void* p) {
    uint32_t a;
    asm("{ .reg .u64 t; cvta.to.shared.u64 t, %1; cvt.u32.u64 %0, t; }"
        : "=r"(a) : "l"(p));
    return a;
}

static __device__ __forceinline__ void ldsm_x4(uint32_t* r, uint32_t addr) {
    asm volatile("ldmatrix.sync.aligned.m8n8.x4.shared.b16 {%0,%1,%2,%3}, [%4];"
                 : "=r"(r[0]), "=r"(r[1]), "=r"(r[2]), "=r"(r[3]) : "r"(addr));
}

static __device__ __forceinline__ void mma16816(float* d, const uint32_t* a,
                                                const uint32_t* b) {
    asm volatile(
        "mma.sync.aligned.m16n8k16.row.col.f32.bf16.bf16.f32 "
        "{%0,%1,%2,%3}, {%4,%5,%6,%7}, {%8,%9}, {%0,%1,%2,%3};"
        : "+f"(d[0]), "+f"(d[1]), "+f"(d[2]), "+f"(d[3])
        : "r"(a[0]), "r"(a[1]), "r"(a[2]), "r"(a[3]), "r"(b[0]), "r"(b[1]));
}

// ---- packed f32x2 ops (Blackwell FFMA2; ptxas never auto-generates) ----
static __device__ __forceinline__ u64 pk(float lo, float hi) {
    u64 r; asm("mov.b64 %0, {%1, %2};" : "=l"(r) : "f"(lo), "f"(hi)); return r;
}
static __device__ __forceinline__ float2 upk(u64 v) {
    float2 f; asm("mov.b64 {%0, %1}, %2;" : "=f"(f.x), "=f"(f.y) : "l"(v)); return f;
}
static __device__ __forceinline__ u64 ffma2(u64 a, u64 b, u64 c) {
    u64 d; asm("fma.rn.f32x2 %0, %1, %2, %3;" : "=l"(d) : "l"(a), "l"(b), "l"(c));
    return d;
}
static __device__ __forceinline__ float ex2f_fast(float x) {
    float y; asm("ex2.approx.ftz.f32 %0, %1;" : "=f"(y) : "f"(x)); return y;
}

// Robust softplus for the target term only (x can be any sign/magnitude).
__device__ __forceinline__ float softplus_full(float x)
{
    if (x > 8.0f) return x + __expf(-x);
    float z = __expf(x);
    if (z < 0.015625f) return z * fmaf(z, fmaf(z, 0.33333334f, -0.5f), 1.0f);
    return __logf(1.0f + z);
}

// convert 8 f32 (two float4) -> 8 bf16 packed in a uint4
static __device__ __forceinline__ uint4 pack8_bf16(float4 a, float4 b)
{
    __nv_bfloat162 h0 = __floats2bfloat162_rn(a.x, a.y);
    __nv_bfloat162 h1 = __floats2bfloat162_rn(a.z, a.w);
    __nv_bfloat162 h2 = __floats2bfloat162_rn(b.x, b.y);
    __nv_bfloat162 h3 = __floats2bfloat162_rn(b.z, b.w);
    uint4 p;
    p.x = *(uint32_t*)&h0; p.y = *(uint32_t*)&h1;
    p.z = *(uint32_t*)&h2; p.w = *(uint32_t*)&h3;
    return p;
}

// ---------------------------------------------------------------------------
// Tiny init kernel: zero the scalar output (stream-ordered before main).
// ---------------------------------------------------------------------------
__global__ void zero_kernel(float* __restrict__ d_out) { d_out[0] = 0.0f; }

// ---------------------------------------------------------------------------
// Fused NCE kernel: one CTA = 128 rows x 64 noise via mma.sync bf16.
//   grid = (50, 16) = 800 CTAs at 4 CTA/SM (~1.35 waves over 592 slots),
//   256 threads / 8 warps; warp w handles rows w*16..w*16+15, all 64 cols.
//   Max-MLP staging; target gather split around the mainloop; packed f32x2
//   epilogue with ex2.approx. Finalization: one atomicAdd per CTA.
// ---------------------------------------------------------------------------
__global__ void __launch_bounds__(NTHREADS, 4)
nce_fused_kernel(const int* __restrict__ target,
                 const float* __restrict__ input,
                 const float* __restrict__ embs,
                 const int* __restrict__ noise_samples,
                 const float* __restrict__ logprob_noise,
                 float norm_c, float inv_rows, float* __restrict__ d_out)
{
    __shared__ __align__(1024) char s_a[A_BYTES];   // 16 KB A (bf16 SW128)
    __shared__ __align__(1024) char s_b[B_BYTES];   // 8 KB  B (bf16 SW128)
    __shared__ __align__(8) float s_c[NT];          // -(c_k * log2e)
    __shared__ float s_red[8];

    const int tid  = threadIdx.x;
    const int lane = tid & 31;
    const int wid  = tid >> 5;          // warp = M-slice: rows wid*16..+15
    const int bm   = blockIdx.x;
    const int bn   = blockIdx.y;

    // ---- early: kick off the target-index load (8 rows per CTA) ----
    int tgt_idx = 0;
    const bool has_tgt = (tid < TROWS);
    const int  trow = bm * MT + bn * TROWS + tid;
    if (has_tgt) tgt_idx = __ldg(&target[trow]);    // arrives during staging

    // ---- staging addresses (thread-invariant swizzle part) ----
    const int rgrp = tid >> 3;          // 0..31
    const int cchk = tid & 7;
    const uint32_t sw_thread =
        (uint32_t)rgrp * 128 + ((uint32_t)((rgrp & 7) ^ cchk) << 4);

    // --- issue ALL staging loads first (max MLP: 12 LDG.128), then cvt+STS ---
    float4 a0[4], a1[4];                 // A: 4 chunks (rows rgrp + i*32)
    {
        const float4* src = (const float4*)(input
            + (size_t)(bm * MT + rgrp) * DIM + cchk * 8);
#pragma unroll
        for (int i = 0; i < 4; i++) {
            a0[i] = src[i * 512];        // i*32 rows * 16 f4/row
            a1[i] = src[i * 512 + 1];
        }
    }
    int nidx[2];
#pragma unroll
    for (int i = 0; i < 2; i++)
        nidx[i] = noise_samples[bn * NT + i * 32 + rgrp];
    float4 b0[2], b1[2];
#pragma unroll
    for (int i = 0; i < 2; i++) {
        const float4* src = (const float4*)(embs + (size_t)nidx[i] * DIM + cchk * 8);
        b0[i] = src[0];
        b1[i] = src[1];
    }
    {
        char* dstA = s_a + sw_thread;
        char* dstB = s_b + sw_thread;
#pragma unroll
        for (int i = 0; i < 4; i++)
            *(uint4*)(dstA + i * 4096) = pack8_bf16(a0[i], a1[i]);
#pragma unroll
        for (int i = 0; i < 2; i++)
            *(uint4*)(dstB + i * 4096) = pack8_bf16(b0[i], b1[i]);
    }
    if (tid < NT) {
        int it = noise_samples[bn * NT + tid];
        s_c[tid] = -(norm_c + logprob_noise[it]) * LOG2E;
    }
    __syncthreads();

    // ---- start the dependent target row load NOW; consume after mainloop ----
    float4 te_reg[4];
    float  tgt_lpn = 0.0f;
    if (has_tgt) {
        const float4* te = (const float4*)(embs + (size_t)tgt_idx * DIM);
#pragma unroll
        for (int i = 0; i < 4; i++) te_reg[i] = __ldg(&te[i]);
        tgt_lpn = __ldg(&logprob_noise[tgt_idx]);
    }

    // ---- LDSM base addresses (XOR-folded SW128) ----
    const uint32_t r7 = lane & 7;
    const uint32_t a_base0 = smem_u32(s_a)
        + (((uint32_t)(wid * 16 + (lane & 15)) * 128)
           ^ (r7 << 4) ^ ((uint32_t)(lane >> 4) << 4));
    const uint32_t b_base0 = smem_u32(s_b)
        + (((uint32_t)((lane & 7) + ((lane >> 4) << 3)) * 128)
           ^ (r7 << 4) ^ ((uint32_t)((lane >> 3) & 1) << 4));

    // --- mainloop: warp = 16 rows x 64 cols, K = 4 x k16 ---
    float acc[8][4] = {};
#pragma unroll
    for (int k = 0; k < 4; k++) {
        uint32_t afr[4];
        ldsm_x4(afr, a_base0 ^ (k << 5));
        uint32_t bfr[8][2];
#pragma unroll
        for (int nj = 0; nj < 4; nj++) {
            uint32_t b4[4];
            ldsm_x4(b4, (b_base0 + nj * 2048) ^ (k << 5));
            bfr[nj * 2][0]     = b4[0]; bfr[nj * 2][1]     = b4[1];
            bfr[nj * 2 + 1][0] = b4[2]; bfr[nj * 2 + 1][1] = b4[3];
        }
#pragma unroll
        for (int ni = 0; ni < 8; ni++)
            mma16816(acc[ni], afr, bfr[ni]);
    }

    // --- packed epilogue: softplus(z) ~= z - z^2/2, z = 2^(s*log2e + nc) ---
    const u64 L2E2 = pk(LOG2E, LOG2E);
    const u64 MH2  = pk(-0.5f, -0.5f);
    const u64 ONE2 = pk(1.0f, 1.0f);
    u64 acc2a = pk(0.0f, 0.0f);
    u64 acc2b = pk(0.0f, 0.0f);
#pragma unroll
    for (int ni = 0; ni < 8; ni++) {
        int col = ni * 8 + (lane & 3) * 2;
        const u64 nc2 = *(const u64*)&s_c[col];     // 8B-aligned LDS.64
        float2 t0 = upk(ffma2(pk(acc[ni][0], acc[ni][1]), L2E2, nc2));
        u64 z0 = pk(ex2f_fast(t0.x), ex2f_fast(t0.y));
        acc2a = ffma2(z0, ffma2(z0, MH2, ONE2), acc2a);
        float2 t1 = upk(ffma2(pk(acc[ni][2], acc[ni][3]), L2E2, nc2));
        u64 z1 = pk(ex2f_fast(t1.x), ex2f_fast(t1.y));
        acc2b = ffma2(z1, ffma2(z1, MH2, ONE2), acc2b);
    }
    float2 fa = upk(acc2a), fb = upk(acc2b);
    float local = (fa.x + fa.y) + (fb.x + fb.y);

    // ---- deferred target term (exact f32; loads long since arrived) ----
    if (has_tgt) {
        const float4* ti = (const float4*)(input + (size_t)trow * DIM);
        float acc_t = 0.0f;
#pragma unroll
        for (int i = 0; i < 4; i++) {
            float4 x = ti[i], e = te_reg[i];
            acc_t = fmaf(x.x, e.x, fmaf(x.y, e.y, fmaf(x.z, e.z, fmaf(x.w, e.w, acc_t))));
        }
        float xt = acc_t - norm_c - tgt_lpn;
        local += softplus_full(-xt);
    }

    // --- block reduction + one atomicAdd per CTA ---
#pragma unroll
    for (int o = 16; o; o >>= 1)
        local += __shfl_xor_sync(0xffffffffu, local, o);
    if (lane == 0) s_red[wid] = local;
    __syncthreads();
    if (tid == 0) {
        float s = 0.0f;
#pragma unroll
        for (int w = 0; w < 8; w++) s += s_red[w];
        atomicAdd(d_out, s * inv_rows);
    }
}

// ---------------------------------------------------------------------------
// Launch. Inputs (metadata order): target i32[6400], input f32[6400*64],
// embs f32[1e6*64], noise_samples i32[1024], logprob_noise f32[1e6].
// Output: f32[1] (mean loss).
// ---------------------------------------------------------------------------
extern "C" void kernel_launch(void* const* d_in, const int* in_sizes, int n_in,
                              void* d_out, int out_size)
{
    const int*   target = (const int*)d_in[0];
    const float* input  = (const float*)d_in[1];
    const float* embs   = (const float*)d_in[2];
    const int*   noise  = (const int*)d_in[3];
    const float* lpn    = (const float*)d_in[4];
    float*       out    = (float*)d_out;

    const int rows = in_sizes[0];                              // 6400
    const float norm_c = logf((float)in_sizes[4]) + logf((float)in_sizes[3]);

    zero_kernel<<<1, 1>>>(out);
    dim3 grid(GRID_M, GRID_N);                                 // 50 x 16
    nce_fused_kernel<<<grid, NTHREADS>>>(target, input, embs, noise, lpn,
                                         norm_c, 1.0f / (float)rows, out);
}

// round 16
// speedup vs baseline: 1.1425x; 1.1425x over previous
#include <cuda_runtime.h>
#include <cuda_bf16.h>
#include <math.h>
#include <stdint.h>

// Shapes (fixed): B*N=6400 rows, K=1024 noise, D=64, V=1e6.
#define DIM        64
#define K_NOISE    1024
#define ROWS_TOT   6400
#define MT         128                 // M tile (rows per CTA)
#define NT         64                  // N tile (noise cols per CTA)
#define A_BYTES    (MT * 128)          // 16 KB
#define B_BYTES    (NT * 128)          // 8 KB
#define GRID_M     (ROWS_TOT / MT)     // 50
#define GRID_N     (K_NOISE / NT)      // 16
#define NTHREADS   256
#define TROWS      (MT / GRID_N)       // 8 target rows per CTA
#define LOG2E      1.4426950408889634f

typedef unsigned long long u64;

// ---------------------------------------------------------------------------
// helpers
// ---------------------------------------------------------------------------
static __device__ __forceinline__ uint32_t smem_u32(const void* p) {
    uint32_t a;
    asm("{ .reg .u64 t; cvta.to.shared.u64 t, %1; cvt.u32.u64 %0, t; }"
        : "=r"(a) : "l"(p));
    return a;
}

static __device__ __forceinline__ void ldsm_x4(uint32_t* r, uint32_t addr) {
    asm volatile("ldmatrix.sync.aligned.m8n8.x4.shared.b16 {%0,%1,%2,%3}, [%4];"
                 : "=r"(r[0]), "=r"(r[1]), "=r"(r[2]), "=r"(r[3]) : "r"(addr));
}

static __device__ __forceinline__ void mma16816(float* d, const uint32_t* a,
                                                const uint32_t* b) {
    asm volatile(
        "mma.sync.aligned.m16n8k16.row.col.f32.bf16.bf16.f32 "
        "{%0,%1,%2,%3}, {%4,%5,%6,%7}, {%8,%9}, {%0,%1,%2,%3};"
        : "+f"(d[0]), "+f"(d[1]), "+f"(d[2]), "+f"(d[3])
        : "r"(a[0]), "r"(a[1]), "r"(a[2]), "r"(a[3]), "r"(b[0]), "r"(b[1]));
}

// ---- packed f32x2 ops (Blackwell FFMA2; ptxas never auto-generates) ----
static __device__ __forceinline__ u64 pk(float lo, float hi) {
    u64 r; asm("mov.b64 %0, {%1, %2};" : "=l"(r) : "f"(lo), "f"(hi)); return r;
}
static __device__ __forceinline__ float2 upk(u64 v) {
    float2 f; asm("mov.b64 {%0, %1}, %2;" : "=f"(f.x), "=f"(f.y) : "l"(v)); return f;
}
static __device__ __forceinline__ u64 ffma2(u64 a, u64 b, u64 c) {
    u64 d; asm("fma.rn.f32x2 %0, %1, %2, %3;" : "=l"(d) : "l"(a), "l"(b), "l"(c));
    return d;
}
static __device__ __forceinline__ float ex2f_fast(float x) {
    float y; asm("ex2.approx.ftz.f32 %0, %1;" : "=f"(y) : "f"(x)); return y;
}

// Robust softplus for the target term only (x can be any sign/magnitude).
__device__ __forceinline__ float softplus_full(float x)
{
    if (x > 8.0f) return x + __expf(-x);
    float z = __expf(x);
    if (z < 0.015625f) return z * fmaf(z, fmaf(z, 0.33333334f, -0.5f), 1.0f);
    return __logf(1.0f + z);
}

// convert 8 f32 (two float4) -> 8 bf16 packed in a uint4
static __device__ __forceinline__ uint4 pack8_bf16(float4 a, float4 b)
{
    __nv_bfloat162 h0 = __floats2bfloat162_rn(a.x, a.y);
    __nv_bfloat162 h1 = __floats2bfloat162_rn(a.z, a.w);
    __nv_bfloat162 h2 = __floats2bfloat162_rn(b.x, b.y);
    __nv_bfloat162 h3 = __floats2bfloat162_rn(b.z, b.w);
    uint4 p;
    p.x = *(uint32_t*)&h0; p.y = *(uint32_t*)&h1;
    p.z = *(uint32_t*)&h2; p.w = *(uint32_t*)&h3;
    return p;
}

// ---------------------------------------------------------------------------
// Tiny init kernel: zero the scalar output (stream-ordered before main).
// ---------------------------------------------------------------------------
__global__ void zero_kernel(float* __restrict__ d_out) { d_out[0] = 0.0f; }

// ---------------------------------------------------------------------------
// Fused NCE kernel: one CTA = 128 rows x 64 noise via mma.sync bf16.
//   grid = (50, 16) = 800 CTAs (~1.8 waves at 3 CTA/SM -> wave pipelining),
//   256 threads / 8 warps; warp w handles rows w*16..w*16+15, all 64 cols.
//   Max-MLP staging; target gather split around the mainloop; packed f32x2
//   epilogue with ex2.approx. Finalization: one atomicAdd per CTA.
// ---------------------------------------------------------------------------
__global__ void __launch_bounds__(NTHREADS, 3)
nce_fused_kernel(const int* __restrict__ target,
                 const float* __restrict__ input,
                 const float* __restrict__ embs,
                 const int* __restrict__ noise_samples,
                 const float* __restrict__ logprob_noise,
                 float norm_c, float inv_rows, float* __restrict__ d_out)
{
    __shared__ __align__(1024) char s_a[A_BYTES];   // 16 KB A (bf16 SW128)
    __shared__ __align__(1024) char s_b[B_BYTES];   // 8 KB  B (bf16 SW128)
    __shared__ __align__(8) float s_c[NT];          // -(c_k * log2e)
    __shared__ float s_red[8];

    const int tid  = threadIdx.x;
    const int lane = tid & 31;
    const int wid  = tid >> 5;          // warp = M-slice: rows wid*16..+15
    const int bm   = blockIdx.x;
    const int bn   = blockIdx.y;

    // ---- early: kick off the target-index load (8 rows per CTA) ----
    int tgt_idx = 0;
    const bool has_tgt = (tid < TROWS);
    const int  trow = bm * MT + bn * TROWS + tid;
    if (has_tgt) tgt_idx = __ldg(&target[trow]);    // arrives during staging

    // ---- staging addresses (thread-invariant swizzle part) ----
    // rgrp = tid>>3 (0..31), cchk = tid&7; row_i = i*32 + rgrp keeps row&7
    // fixed, so the swizzled smem offset is sw_thread + i*4096.
    const int rgrp = tid >> 3;
    const int cchk = tid & 7;
    const uint32_t sw_thread =
        (uint32_t)rgrp * 128 + ((uint32_t)((rgrp & 7) ^ cchk) << 4);

    // --- issue ALL staging loads first (max MLP: 12 LDG.128), then cvt+STS ---
    float4 a0[4], a1[4];                 // A: 4 chunks (rows rgrp + i*32)
    {
        const float4* src = (const float4*)(input
            + (size_t)(bm * MT + rgrp) * DIM + cchk * 8);
#pragma unroll
        for (int i = 0; i < 4; i++) {
            a0[i] = src[i * 512];        // i*32 rows * 16 f4/row
            a1[i] = src[i * 512 + 1];
        }
    }
    int nidx[2];
#pragma unroll
    for (int i = 0; i < 2; i++)
        nidx[i] = noise_samples[bn * NT + i * 32 + rgrp];
    float4 b0[2], b1[2];
#pragma unroll
    for (int i = 0; i < 2; i++) {
        const float4* src = (const float4*)(embs + (size_t)nidx[i] * DIM + cchk * 8);
        b0[i] = src[0];
        b1[i] = src[1];
    }
    {
        char* dstA = s_a + sw_thread;
        char* dstB = s_b + sw_thread;
#pragma unroll
        for (int i = 0; i < 4; i++)
            *(uint4*)(dstA + i * 4096) = pack8_bf16(a0[i], a1[i]);
#pragma unroll
        for (int i = 0; i < 2; i++)
            *(uint4*)(dstB + i * 4096) = pack8_bf16(b0[i], b1[i]);
    }
    if (tid < NT) {
        int it = noise_samples[bn * NT + tid];
        s_c[tid] = -(norm_c + logprob_noise[it]) * LOG2E;
    }
    __syncthreads();

    // ---- start the dependent target row load NOW; consume after mainloop ----
    float4 te_reg[4];
    float  tgt_lpn = 0.0f;
    if (has_tgt) {
        const float4* te = (const float4*)(embs + (size_t)tgt_idx * DIM);
#pragma unroll
        for (int i = 0; i < 4; i++) te_reg[i] = __ldg(&te[i]);
        tgt_lpn = __ldg(&logprob_noise[tgt_idx]);
    }

    // ---- LDSM base addresses (XOR-folded SW128) ----
    const uint32_t r7 = lane & 7;
    const uint32_t a_base0 = smem_u32(s_a)
        + (((uint32_t)(wid * 16 + (lane & 15)) * 128)
           ^ (r7 << 4) ^ ((uint32_t)(lane >> 4) << 4));
    const uint32_t b_base0 = smem_u32(s_b)
        + (((uint32_t)((lane & 7) + ((lane >> 4) << 3)) * 128)
           ^ (r7 << 4) ^ ((uint32_t)((lane >> 3) & 1) << 4));

    // --- mainloop: warp = 16 rows x 64 cols, K = 4 x k16 ---
    float acc[8][4] = {};
#pragma unroll
    for (int k = 0; k < 4; k++) {
        uint32_t afr[4];
        ldsm_x4(afr, a_base0 ^ (k << 5));
        uint32_t bfr[8][2];
#pragma unroll
        for (int nj = 0; nj < 4; nj++) {
            uint32_t b4[4];
            ldsm_x4(b4, (b_base0 + nj * 2048) ^ (k << 5));
            bfr[nj * 2][0]     = b4[0]; bfr[nj * 2][1]     = b4[1];
            bfr[nj * 2 + 1][0] = b4[2]; bfr[nj * 2 + 1][1] = b4[3];
        }
#pragma unroll
        for (int ni = 0; ni < 8; ni++)
            mma16816(acc[ni], afr, bfr[ni]);
    }

    // --- packed epilogue: softplus(z) ~= z - z^2/2, z = 2^(s*log2e + nc) ---
    const u64 L2E2 = pk(LOG2E, LOG2E);
    const u64 MH2  = pk(-0.5f, -0.5f);
    const u64 ONE2 = pk(1.0f, 1.0f);
    u64 acc2a = pk(0.0f, 0.0f);
    u64 acc2b = pk(0.0f, 0.0f);
#pragma unroll
    for (int ni = 0; ni < 8; ni++) {
        int col = ni * 8 + (lane & 3) * 2;
        const u64 nc2 = *(const u64*)&s_c[col];     // 8B-aligned LDS.64
        float2 t0 = upk(ffma2(pk(acc[ni][0], acc[ni][1]), L2E2, nc2));
        u64 z0 = pk(ex2f_fast(t0.x), ex2f_fast(t0.y));
        acc2a = ffma2(z0, ffma2(z0, MH2, ONE2), acc2a);
        float2 t1 = upk(ffma2(pk(acc[ni][2], acc[ni][3]), L2E2, nc2));
        u64 z1 = pk(ex2f_fast(t1.x), ex2f_fast(t1.y));
        acc2b = ffma2(z1, ffma2(z1, MH2, ONE2), acc2b);
    }
    float2 fa = upk(acc2a), fb = upk(acc2b);
    float local = (fa.x + fa.y) + (fb.x + fb.y);

    // ---- deferred target term (exact f32; loads long since arrived) ----
    if (has_tgt) {
        const float4* ti = (const float4*)(input + (size_t)trow * DIM);
        float acc_t = 0.0f;
#pragma unroll
        for (int i = 0; i < 4; i++) {
            float4 x = ti[i], e = te_reg[i];
            acc_t = fmaf(x.x, e.x, fmaf(x.y, e.y, fmaf(x.z, e.z, fmaf(x.w, e.w, acc_t))));
        }
        float xt = acc_t - norm_c - tgt_lpn;
        local += softplus_full(-xt);
    }

    // --- block reduction + one atomicAdd per CTA ---
#pragma unroll
    for (int o = 16; o; o >>= 1)
        local += __shfl_xor_sync(0xffffffffu, local, o);
    if (lane == 0) s_red[wid] = local;
    __syncthreads();
    if (tid == 0) {
        float s = 0.0f;
#pragma unroll
        for (int w = 0; w < 8; w++) s += s_red[w];
        atomicAdd(d_out, s * inv_rows);
    }
}

// ---------------------------------------------------------------------------
// Launch. Inputs (metadata order): target i32[6400], input f32[6400*64],
// embs f32[1e6*64], noise_samples i32[1024], logprob_noise f32[1e6].
// Output: f32[1] (mean loss).
// ---------------------------------------------------------------------------
extern "C" void kernel_launch(void* const* d_in, const int* in_sizes, int n_in,
                              void* d_out, int out_size)
{
    const int*   target = (const int*)d_in[0];
    const float* input  = (const float*)d_in[1];
    const float* embs   = (const float*)d_in[2];
    const int*   noise  = (const int*)d_in[3];
    const float* lpn    = (const float*)d_in[4];
    float*       out    = (float*)d_out;

    const int rows = in_sizes[0];                              // 6400
    const float norm_c = logf((float)in_sizes[4]) + logf((float)in_sizes[3]);

    zero_kernel<<<1, 1>>>(out);
    dim3 grid(GRID_M, GRID_N);                                 // 50 x 16
    nce_fused_kernel<<<grid, NTHREADS>>>(target, input, embs, noise, lpn,
                                         norm_c, 1.0f / (float)rows, out);
}